// round 4
// baseline (speedup 1.0000x reference)
#include <cuda_runtime.h>
#include <math.h>

// Problem constants
#define N_    512
#define V_    6890
#define NJ_   24
#define NB_   10
#define KD_   218            // 207 pose + 10 scale*betas + 1 scale
#define Q_    (V_*3)         // 20670
#define NK_   95
#define NC_   (N_*3)         // 1536

// pass1 tiling: block 64n x 384q (128 verts), 256 threads, thread 16n x 6q
#define P1_QB  54            // ceil(20670/384)
// pass2 split-K
#define NSPLIT2 24
#define KCH2    288          // ceil(6890/24)

// ------------------------------- scratch -----------------------------------
__device__ float g_JT[NJ_*3];
__device__ float g_JS[NB_*NJ_*3];
__device__ float g_coeffT[KD_*N_];          // [k][n]
__device__ float g_AT[NJ_*12*N_];           // [j*12+e][n]
__device__ float g_verts[V_*NC_];           // [v][n*3+c]
__device__ float g_RT[V_*96];               // transposed regressors [v][m] (m=95 padded to 96)
__device__ float g_part[NSPLIT2*NK_*NC_];

// ------------------------- packed f32x2 helpers -----------------------------
typedef unsigned long long u64;
__device__ __forceinline__ u64 fma2(u64 a, u64 b, u64 c) {
    u64 d; asm("fma.rn.f32x2 %0, %1, %2, %3;" : "=l"(d) : "l"(a), "l"(b), "l"(c)); return d;
}
__device__ __forceinline__ u64 dup2(float x) {
    u64 r; asm("mov.b64 %0, {%1, %1};" : "=l"(r) : "f"(x)); return r;
}
__device__ __forceinline__ float2 unpk2(u64 v) {
    float2 r; asm("mov.b64 {%0, %1}, %2;" : "=f"(r.x), "=f"(r.y) : "l"(v)); return r;
}

// ---------------------------------------------------------------------------
// K1: joint-regressor constants
// ---------------------------------------------------------------------------
__global__ void k_jconst(const float* __restrict__ Jreg,
                         const float* __restrict__ vt,
                         const float* __restrict__ sd) {
    int o = blockIdx.x;              // 0..791  (72 JT + 720 JS)
    int tid = threadIdx.x;
    float s = 0.f;
    if (o < 72) {
        int j = o / 3, c = o % 3;
        const float* jr = Jreg + (size_t)j * V_;
        for (int v = tid; v < V_; v += 256) s += jr[v] * vt[v*3 + c];
    } else {
        int r = o - 72;
        int b = r / 72; int r2 = r % 72;
        int j = r2 / 3, c = r2 % 3;
        const float* jr = Jreg + (size_t)j * V_;
        const float* sp = sd + (size_t)b * Q_;
        for (int v = tid; v < V_; v += 256) s += jr[v] * sp[v*3 + c];
    }
    __shared__ float red[8];
    for (int off = 16; off > 0; off >>= 1) s += __shfl_down_sync(0xffffffffu, s, off);
    if ((tid & 31) == 0) red[tid >> 5] = s;
    __syncthreads();
    if (tid == 0) {
        float t = 0.f;
        #pragma unroll
        for (int w = 0; w < 8; w++) t += red[w];
        if (o < 72) g_JT[o] = t;
        else        g_JS[o - 72] = t;
    }
}

// ---------------------------------------------------------------------------
// K2: per-n scale, coeff (transposed), FK -> A (transposed [e][n])
// ---------------------------------------------------------------------------
__global__ void k_pern(const float* __restrict__ pose,
                       const float* __restrict__ betas,
                       const float* __restrict__ vt,
                       const float* __restrict__ sd,
                       const int*   __restrict__ parents) {
    int n = blockIdx.x * blockDim.x + threadIdx.x;
    if (n >= N_) return;
    const float* be = betas + n * NB_;

    const int   iv[4]  = {2802, 6262, 2237, 6728};
    const float sg[4]  = {1.f, 1.f, -1.f, -1.f};
    float bh = 0.f;
    #pragma unroll
    for (int t = 0; t < 4; t++) {
        int q = iv[t]*3 + 1;
        float vy = vt[q];
        #pragma unroll
        for (int b = 0; b < NB_; b++) vy += be[b] * sd[(size_t)b*Q_ + q];
        bh += sg[t] * vy;
    }
    float scale = 1.66f / bh;

    const float* pn = pose + (size_t)n * NJ_ * 9;
    for (int j = 1; j < NJ_; j++) {
        #pragma unroll
        for (int e = 0; e < 9; e++) {
            float d = (e == 0 || e == 4 || e == 8) ? 1.f : 0.f;
            g_coeffT[((j-1)*9 + e)*N_ + n] = pn[j*9 + e] - d;
        }
    }
    #pragma unroll
    for (int b = 0; b < NB_; b++) g_coeffT[(207 + b)*N_ + n] = scale * be[b];
    g_coeffT[217*N_ + n] = scale;

    float Jl[NJ_][3];
    for (int j = 0; j < NJ_; j++) {
        #pragma unroll
        for (int c = 0; c < 3; c++) {
            float s = g_JT[j*3 + c];
            #pragma unroll
            for (int b = 0; b < NB_; b++) s += be[b] * g_JS[b*72 + j*3 + c];
            Jl[j][c] = scale * s;
        }
    }

    float Rg[NJ_][9], tg[NJ_][3];
    for (int i = 0; i < NJ_; i++) {
        float Ri[9];
        #pragma unroll
        for (int e = 0; e < 9; e++) Ri[e] = pn[i*9 + e];
        if (i == 0) {
            #pragma unroll
            for (int e = 0; e < 9; e++) Rg[0][e] = Ri[e];
            #pragma unroll
            for (int c = 0; c < 3; c++) tg[0][c] = Jl[0][c];
        } else {
            int p = parents[i];
            float jh[3] = {Jl[i][0]-Jl[p][0], Jl[i][1]-Jl[p][1], Jl[i][2]-Jl[p][2]};
            #pragma unroll
            for (int r = 0; r < 3; r++) {
                float p0 = Rg[p][r*3+0], p1 = Rg[p][r*3+1], p2 = Rg[p][r*3+2];
                #pragma unroll
                for (int c = 0; c < 3; c++)
                    Rg[i][r*3+c] = p0*Ri[c] + p1*Ri[3+c] + p2*Ri[6+c];
                tg[i][r] = tg[p][r] + p0*jh[0] + p1*jh[1] + p2*jh[2];
            }
        }
        #pragma unroll
        for (int r = 0; r < 3; r++) {
            g_AT[(i*12 + r*4 + 0)*N_ + n] = Rg[i][r*3+0];
            g_AT[(i*12 + r*4 + 1)*N_ + n] = Rg[i][r*3+1];
            g_AT[(i*12 + r*4 + 2)*N_ + n] = Rg[i][r*3+2];
            g_AT[(i*12 + r*4 + 3)*N_ + n] = tg[i][r] - (Rg[i][r*3+0]*Jl[i][0] +
                                                        Rg[i][r*3+1]*Jl[i][1] +
                                                        Rg[i][r*3+2]*Jl[i][2]);
        }
    }
}

// ---------------------------------------------------------------------------
// K3: transpose keypoint regressors -> g_RT[v][96] (row 95 zero)
// ---------------------------------------------------------------------------
__global__ void k_transpose(const float* __restrict__ b25,
                            const float* __restrict__ face) {
    int idx = blockIdx.x * 256 + threadIdx.x;
    if (idx >= V_*96) return;
    int v = idx / 96, m = idx - v*96;
    float val = 0.f;
    if (m < 25)      val = b25[(size_t)m*V_ + v];
    else if (m < 95) val = face[(size_t)(m-25)*V_ + v];
    g_RT[idx] = val;
}

// ---------------------------------------------------------------------------
// K4 (pass1): f32x2 GEMM [64n x 384q, K=218] + packed LBS epilogue
// smem union: GEMM {cfs[224][64], Bs[16][384]} | EPI {A_p[288][64], ws[128][25], trT[3][64]}
// ---------------------------------------------------------------------------
#define CFS_ROWS 224
#define SM1_FLOATS (288*64 + 128*25 + 3*64)   // 21824 (epi phase is larger)

__global__ void __launch_bounds__(256, 1)
k_pass1(const float* __restrict__ posedirs,
        const float* __restrict__ shapedirs,
        const float* __restrict__ vtempl,
        const float* __restrict__ lw,
        const float* __restrict__ trans) {
    extern __shared__ float sm[];
    float* cfs = sm;                     // [224][64]
    float* Bs  = sm + CFS_ROWS*64;       // [16][384]
    float* A_p = sm;                     // [288][64]
    float* ws  = sm + 288*64;            // [128][25]
    float* trT = sm + 288*64 + 128*25;   // [3][64]

    int tid = threadIdx.x;
    int q0 = blockIdx.x * 384;
    int v0 = blockIdx.x * 128;
    int n0 = blockIdx.y * 64;
    int row = tid >> 6, col = tid & 63;
    int nb  = row * 16;

    // stage full coeff chunk (transposed), zero-padded to 224 rows
    for (int idx = tid; idx < CFS_ROWS*64; idx += 256) {
        int k = idx >> 6, nn = idx & 63;
        cfs[idx] = (k < KD_) ? g_coeffT[k*N_ + n0 + nn] : 0.f;
    }

    u64 acc[8][6];
    #pragma unroll
    for (int i = 0; i < 8; i++)
        #pragma unroll
        for (int j = 0; j < 6; j++) acc[i][j] = 0ULL;

    for (int kc = 0; kc < CFS_ROWS; kc += 16) {
        __syncthreads();
        // stage B chunk [16][384]
        for (int idx = tid; idx < 16*384; idx += 256) {
            int kk = idx / 384, qq = idx - kk*384;
            int k = kc + kk, q = q0 + qq;
            float val = 0.f;
            if (q < Q_ && k < KD_) {
                if (k < 207)      val = posedirs[(size_t)k*Q_ + q];
                else if (k < 217) val = shapedirs[(size_t)(k-207)*Q_ + q];
                else              val = vtempl[q];
            }
            Bs[idx] = val;
        }
        __syncthreads();
        #pragma unroll 2
        for (int kk = 0; kk < 16; kk++) {
            const float* cr = &cfs[(kc+kk)*64 + nb];
            ulonglong2 A0 = *(const ulonglong2*)(cr);
            ulonglong2 A1 = *(const ulonglong2*)(cr + 4);
            ulonglong2 A2 = *(const ulonglong2*)(cr + 8);
            ulonglong2 A3 = *(const ulonglong2*)(cr + 12);
            u64 a2[8] = {A0.x, A0.y, A1.x, A1.y, A2.x, A2.y, A3.x, A3.y};
            const float* br = &Bs[kk*384 + col*6];
            #pragma unroll
            for (int qi = 0; qi < 6; qi++) {
                u64 b2 = dup2(br[qi]);
                #pragma unroll
                for (int np = 0; np < 8; np++)
                    acc[np][qi] = fma2(a2[np], b2, acc[np][qi]);
            }
        }
    }
    __syncthreads();

    // ---- stage epilogue data (reuses GEMM smem) ----
    for (int idx = tid; idx < 288*64; idx += 256)
        A_p[idx] = g_AT[(size_t)(idx >> 6)*N_ + n0 + (idx & 63)];
    for (int idx = tid; idx < 128*24; idx += 256) {
        int vloc = idx / 24, j = idx - vloc*24;
        int v = v0 + vloc;
        ws[vloc*25 + j] = (v < V_) ? lw[(size_t)v*NJ_ + j] : 0.f;
    }
    if (tid < 192) trT[(tid % 3)*64 + tid/3] = trans[(n0 + tid/3)*3 + (tid % 3)];
    __syncthreads();

    // ---- packed LBS: vr init = trans, accumulate over 24 joints ----
    #pragma unroll
    for (int vsel = 0; vsel < 2; vsel++) {
        int vloc = col*2 + vsel;
        u64 vr[8][3];
        #pragma unroll
        for (int np = 0; np < 8; np++)
            #pragma unroll
            for (int r = 0; r < 3; r++)
                vr[np][r] = *(const u64*)&trT[r*64 + nb + np*2];

        for (int j = 0; j < NJ_; j++) {
            u64 w2 = dup2(ws[vloc*25 + j]);
            const float* ab = &A_p[(j*12)*64 + nb];
            #pragma unroll
            for (int np = 0; np < 8; np++) {
                u64 x2 = acc[np][vsel*3 + 0];
                u64 y2 = acc[np][vsel*3 + 1];
                u64 z2 = acc[np][vsel*3 + 2];
                #pragma unroll
                for (int r = 0; r < 3; r++) {
                    const float* ae = ab + (r*4)*64 + np*2;
                    u64 t = *(const u64*)(ae + 3*64);
                    t = fma2(*(const u64*)(ae),         x2, t);
                    t = fma2(*(const u64*)(ae +  64),   y2, t);
                    t = fma2(*(const u64*)(ae + 128),   z2, t);
                    vr[np][r] = fma2(w2, t, vr[np][r]);
                }
            }
        }
        int v = v0 + vloc;
        if (v < V_) {
            float* dst = g_verts + (size_t)v*NC_ + (n0 + nb)*3;
            #pragma unroll
            for (int np = 0; np < 8; np += 2) {
                float2 p0 = unpk2(vr[np][0]),   p1 = unpk2(vr[np][1]),   p2 = unpk2(vr[np][2]);
                float2 r0 = unpk2(vr[np+1][0]), r1 = unpk2(vr[np+1][1]), r2 = unpk2(vr[np+1][2]);
                float4* d4 = (float4*)(dst + np*6);
                d4[0] = make_float4(p0.x, p1.x, p2.x, p0.y);
                d4[1] = make_float4(p1.y, p2.y, r0.x, r1.x);
                d4[2] = make_float4(r2.x, r0.y, r1.y, r2.y);
            }
        }
    }
}

// ---------------------------------------------------------------------------
// K5 (pass2): packed keypoint GEMM [96 x 1536], split-K x24
// block: 96m x 128c, thread 6m x 4 col-pairs (interleaved, conflict-free LDS.64)
// ---------------------------------------------------------------------------
__global__ void __launch_bounds__(256, 2)
k_pass2() {
    __shared__ float rT[16*96];
    __shared__ float vs[16*128];
    int tid = threadIdx.x;
    int tx = tid & 15, ty = tid >> 4;
    int col0 = blockIdx.x * 128;
    int sp = blockIdx.y;
    int vbeg = sp * KCH2;
    int vend = min(V_, vbeg + KCH2);

    u64 acc[6][4];
    #pragma unroll
    for (int r = 0; r < 6; r++)
        #pragma unroll
        for (int i = 0; i < 4; i++) acc[r][i] = 0ULL;

    for (int kb = vbeg; kb < vend; kb += 16) {
        int kn = min(16, vend - kb);
        __syncthreads();
        for (int idx = tid; idx < 16*96; idx += 256) {
            int kk = idx / 96, mm = idx - kk*96;
            rT[idx] = (kk < kn) ? g_RT[(size_t)(kb+kk)*96 + mm] : 0.f;
        }
        for (int idx = tid; idx < 16*128; idx += 256) {
            int kk = idx >> 7, cc = idx & 127;
            vs[idx] = (kk < kn) ? g_verts[(size_t)(kb+kk)*NC_ + col0 + cc] : 0.f;
        }
        __syncthreads();
        #pragma unroll 4
        for (int kk = 0; kk < 16; kk++) {
            u64 b2[4];
            #pragma unroll
            for (int i = 0; i < 4; i++)
                b2[i] = *(const u64*)&vs[kk*128 + 2*(tx + i*16)];
            #pragma unroll
            for (int r = 0; r < 6; r++) {
                u64 a2 = dup2(rT[kk*96 + ty*6 + r]);
                #pragma unroll
                for (int i = 0; i < 4; i++)
                    acc[r][i] = fma2(a2, b2[i], acc[r][i]);
            }
        }
    }
    float* pp = g_part + (size_t)sp * (NK_*NC_);
    #pragma unroll
    for (int r = 0; r < 6; r++) {
        int m = ty*6 + r;
        if (m < NK_) {
            #pragma unroll
            for (int i = 0; i < 4; i++) {
                float2 p = unpk2(acc[r][i]);
                *(float2*)&pp[(size_t)m*NC_ + col0 + 2*(tx + i*16)] = p;
            }
        }
    }
}

// ---------------------------------------------------------------------------
// K6: reduce split-K partials -> out[n][m][c]
// ---------------------------------------------------------------------------
__global__ void k_reduce(float* __restrict__ out) {
    int o = blockIdx.x * 256 + threadIdx.x;
    if (o >= NK_*NC_) return;
    float s = 0.f;
    #pragma unroll
    for (int sp = 0; sp < NSPLIT2; sp++) s += g_part[(size_t)sp*(NK_*NC_) + o];
    int m = o / NC_, c2 = o % NC_;
    int n = c2 / 3, c = c2 % 3;
    out[(size_t)n*(NK_*3) + m*3 + c] = s;
}

// ---------------------------------------------------------------------------
extern "C" void kernel_launch(void* const* d_in, const int* in_sizes, int n_in,
                              void* d_out, int out_size) {
    const float* pose      = (const float*)d_in[0];
    const float* betas     = (const float*)d_in[1];
    const float* trans     = (const float*)d_in[2];
    const float* vtempl    = (const float*)d_in[3];
    const float* shapedirs = (const float*)d_in[4];
    const float* Jreg      = (const float*)d_in[5];
    const float* posedirs  = (const float*)d_in[6];
    const float* lw        = (const float*)d_in[7];
    const float* body25    = (const float*)d_in[8];
    const float* face      = (const float*)d_in[9];
    const int*   parents   = (const int*)d_in[10];

    (void)in_sizes; (void)n_in; (void)out_size;

    static const int SM1 = SM1_FLOATS * sizeof(float);   // 87296 B
    cudaFuncSetAttribute(k_pass1, cudaFuncAttributeMaxDynamicSharedMemorySize, SM1);

    k_jconst<<<72 + NB_*72, 256>>>(Jreg, vtempl, shapedirs);
    k_pern<<<N_/256, 256>>>(pose, betas, vtempl, shapedirs, parents);
    k_transpose<<<(V_*96 + 255)/256, 256>>>(body25, face);
    k_pass1<<<dim3(P1_QB, N_/64), 256, SM1>>>(posedirs, shapedirs, vtempl, lw, trans);
    k_pass2<<<dim3(NC_/128, NSPLIT2), 256>>>();
    k_reduce<<<(NK_*NC_ + 255)/256, 256>>>((float*)d_out);
}

// round 8
// speedup vs baseline: 1.0205x; 1.0205x over previous
#include <cuda_runtime.h>
#include <math.h>

// Problem constants
#define N_    512
#define V_    6890
#define NJ_   24
#define NB_   10
#define KD_   218
#define Q_    (V_*3)         // 20670
#define NK_   95
#define NC_   (N_*3)         // 1536

#define P1_QB  54            // ceil(20670/384)
#define NSPLIT2 24
#define KCH2    288

// ------------------------------- scratch -----------------------------------
__device__ float g_JT[NJ_*3];
__device__ float g_JS[NB_*NJ_*3];
__device__ float g_coeffT[KD_*N_];          // [k][n]
__device__ float g_AT[NJ_*12*N_];           // [j*12+e][n]
__device__ float g_verts[V_*NC_];           // [v][n*3+c]
__device__ float g_RT[V_*96];               // [v][m], m padded to 96
__device__ float g_part[NSPLIT2*NK_*NC_];

// ------------------------- packed f32x2 helpers -----------------------------
typedef unsigned long long u64;
__device__ __forceinline__ u64 fma2(u64 a, u64 b, u64 c) {
    u64 d; asm("fma.rn.f32x2 %0, %1, %2, %3;" : "=l"(d) : "l"(a), "l"(b), "l"(c)); return d;
}
__device__ __forceinline__ u64 dup2(float x) {
    u64 r; asm("mov.b64 %0, {%1, %1};" : "=l"(r) : "f"(x)); return r;
}
__device__ __forceinline__ float2 unpk2(u64 v) {
    float2 r; asm("mov.b64 {%0, %1}, %2;" : "=f"(r.x), "=f"(r.y) : "l"(v)); return r;
}

// ---------------------------------------------------------------------------
// K1: joint-regressor constants
// ---------------------------------------------------------------------------
__global__ void k_jconst(const float* __restrict__ Jreg,
                         const float* __restrict__ vt,
                         const float* __restrict__ sd) {
    int o = blockIdx.x;
    int tid = threadIdx.x;
    float s = 0.f;
    if (o < 72) {
        int j = o / 3, c = o % 3;
        const float* jr = Jreg + (size_t)j * V_;
        for (int v = tid; v < V_; v += 256) s += jr[v] * vt[v*3 + c];
    } else {
        int r = o - 72;
        int b = r / 72; int r2 = r % 72;
        int j = r2 / 3, c = r2 % 3;
        const float* jr = Jreg + (size_t)j * V_;
        const float* sp = sd + (size_t)b * Q_;
        for (int v = tid; v < V_; v += 256) s += jr[v] * sp[v*3 + c];
    }
    __shared__ float red[8];
    for (int off = 16; off > 0; off >>= 1) s += __shfl_down_sync(0xffffffffu, s, off);
    if ((tid & 31) == 0) red[tid >> 5] = s;
    __syncthreads();
    if (tid == 0) {
        float t = 0.f;
        #pragma unroll
        for (int w = 0; w < 8; w++) t += red[w];
        if (o < 72) g_JT[o] = t;
        else        g_JS[o - 72] = t;
    }
}

// ---------------------------------------------------------------------------
// K2: per-n scale, coeff (transposed), FK -> A (transposed [e][n])
// ---------------------------------------------------------------------------
__global__ void k_pern(const float* __restrict__ pose,
                       const float* __restrict__ betas,
                       const float* __restrict__ vt,
                       const float* __restrict__ sd,
                       const int*   __restrict__ parents) {
    int n = blockIdx.x * blockDim.x + threadIdx.x;
    if (n >= N_) return;
    const float* be = betas + n * NB_;

    const int   iv[4]  = {2802, 6262, 2237, 6728};
    const float sg[4]  = {1.f, 1.f, -1.f, -1.f};
    float bh = 0.f;
    #pragma unroll
    for (int t = 0; t < 4; t++) {
        int q = iv[t]*3 + 1;
        float vy = vt[q];
        #pragma unroll
        for (int b = 0; b < NB_; b++) vy += be[b] * sd[(size_t)b*Q_ + q];
        bh += sg[t] * vy;
    }
    float scale = 1.66f / bh;

    const float* pn = pose + (size_t)n * NJ_ * 9;
    for (int j = 1; j < NJ_; j++) {
        #pragma unroll
        for (int e = 0; e < 9; e++) {
            float d = (e == 0 || e == 4 || e == 8) ? 1.f : 0.f;
            g_coeffT[((j-1)*9 + e)*N_ + n] = pn[j*9 + e] - d;
        }
    }
    #pragma unroll
    for (int b = 0; b < NB_; b++) g_coeffT[(207 + b)*N_ + n] = scale * be[b];
    g_coeffT[217*N_ + n] = scale;

    float Jl[NJ_][3];
    for (int j = 0; j < NJ_; j++) {
        #pragma unroll
        for (int c = 0; c < 3; c++) {
            float s = g_JT[j*3 + c];
            #pragma unroll
            for (int b = 0; b < NB_; b++) s += be[b] * g_JS[b*72 + j*3 + c];
            Jl[j][c] = scale * s;
        }
    }

    float Rg[NJ_][9], tg[NJ_][3];
    for (int i = 0; i < NJ_; i++) {
        float Ri[9];
        #pragma unroll
        for (int e = 0; e < 9; e++) Ri[e] = pn[i*9 + e];
        if (i == 0) {
            #pragma unroll
            for (int e = 0; e < 9; e++) Rg[0][e] = Ri[e];
            #pragma unroll
            for (int c = 0; c < 3; c++) tg[0][c] = Jl[0][c];
        } else {
            int p = parents[i];
            float jh[3] = {Jl[i][0]-Jl[p][0], Jl[i][1]-Jl[p][1], Jl[i][2]-Jl[p][2]};
            #pragma unroll
            for (int r = 0; r < 3; r++) {
                float p0 = Rg[p][r*3+0], p1 = Rg[p][r*3+1], p2 = Rg[p][r*3+2];
                #pragma unroll
                for (int c = 0; c < 3; c++)
                    Rg[i][r*3+c] = p0*Ri[c] + p1*Ri[3+c] + p2*Ri[6+c];
                tg[i][r] = tg[p][r] + p0*jh[0] + p1*jh[1] + p2*jh[2];
            }
        }
        #pragma unroll
        for (int r = 0; r < 3; r++) {
            g_AT[(i*12 + r*4 + 0)*N_ + n] = Rg[i][r*3+0];
            g_AT[(i*12 + r*4 + 1)*N_ + n] = Rg[i][r*3+1];
            g_AT[(i*12 + r*4 + 2)*N_ + n] = Rg[i][r*3+2];
            g_AT[(i*12 + r*4 + 3)*N_ + n] = tg[i][r] - (Rg[i][r*3+0]*Jl[i][0] +
                                                        Rg[i][r*3+1]*Jl[i][1] +
                                                        Rg[i][r*3+2]*Jl[i][2]);
        }
    }
}

// ---------------------------------------------------------------------------
// K3: transpose keypoint regressors -> g_RT[v][96]
// ---------------------------------------------------------------------------
__global__ void k_transpose(const float* __restrict__ b25,
                            const float* __restrict__ face) {
    int idx = blockIdx.x * 256 + threadIdx.x;
    if (idx >= V_*96) return;
    int v = idx / 96, m = idx - v*96;
    float val = 0.f;
    if (m < 25)      val = b25[(size_t)m*V_ + v];
    else if (m < 95) val = face[(size_t)(m-25)*V_ + v];
    g_RT[idx] = val;
}

// ---------------------------------------------------------------------------
// K4 (pass1): f32x2 GEMM [32n x 384q, K=218] + packed LBS epilogue
// thread tile: 4 n-pairs x 6 q. launch_bounds(256,2) -> <=128 regs, 2 blk/SM.
// smem union: GEMM {cfs[224][32], Bs[16][384]} | EPI {A_p[24][16][3][8], ws[128][25], trT[3][32]}
// ---------------------------------------------------------------------------
#define CFS_ROWS 224
#define SM1_FLOATS (CFS_ROWS*32 + 16*384)     // 13312 floats (GEMM phase is larger)

__global__ void __launch_bounds__(256, 2)
k_pass1(const float* __restrict__ posedirs,
        const float* __restrict__ shapedirs,
        const float* __restrict__ vtempl,
        const float* __restrict__ lw,
        const float* __restrict__ trans) {
    extern __shared__ float sm[];
    float* cfs = sm;                     // [224][32]
    float* Bs  = sm + CFS_ROWS*32;       // [16][384]
    float* A_p = sm;                     // [24][16][3][8] = 9216
    float* ws  = sm + 9216;              // [128][25] = 3200
    float* trT = sm + 9216 + 3200;       // [3][32]

    int tid = threadIdx.x;
    int q0 = blockIdx.x * 384;
    int v0 = blockIdx.x * 128;
    int n0 = blockIdx.y * 32;
    int ty  = tid >> 6;                  // 0..3 (n-group of 8)
    int col = tid & 63;                  // q-group of 6
    int nb  = ty * 8;

    // ---- stage coeff (transposed), zero-padded to 224 rows ----
    for (int idx = tid; idx < CFS_ROWS*32; idx += 256) {
        int k = idx >> 5, nn = idx & 31;
        cfs[idx] = (k < KD_) ? g_coeffT[k*N_ + n0 + nn] : 0.f;
    }

    u64 acc[4][6];
    #pragma unroll
    for (int i = 0; i < 4; i++)
        #pragma unroll
        for (int j = 0; j < 6; j++) acc[i][j] = 0ULL;

    for (int kc = 0; kc < CFS_ROWS; kc += 16) {
        __syncthreads();
        for (int idx = tid; idx < 16*384; idx += 256) {
            int kk = idx / 384, qq = idx - kk*384;
            int k = kc + kk, q = q0 + qq;
            float val = 0.f;
            if (q < Q_ && k < KD_) {
                if (k < 207)      val = posedirs[(size_t)k*Q_ + q];
                else if (k < 217) val = shapedirs[(size_t)(k-207)*Q_ + q];
                else              val = vtempl[q];
            }
            Bs[idx] = val;
        }
        __syncthreads();
        #pragma unroll 4
        for (int kk = 0; kk < 16; kk++) {
            const float* cr = &cfs[(kc+kk)*32 + nb];
            ulonglong2 A0 = *(const ulonglong2*)(cr);
            ulonglong2 A1 = *(const ulonglong2*)(cr + 4);
            u64 a2[4] = {A0.x, A0.y, A1.x, A1.y};
            const float* br = &Bs[kk*384 + col*6];
            #pragma unroll
            for (int qi = 0; qi < 6; qi++) {
                u64 b2 = dup2(br[qi]);
                #pragma unroll
                for (int np = 0; np < 4; np++)
                    acc[np][qi] = fma2(a2[np], b2, acc[np][qi]);
            }
        }
    }
    __syncthreads();

    // ---- stage epilogue data (reuses GEMM smem) ----
    // A_p layout: [j][npair(16)][r(3)][Ax0,Ax1,Ay0,Ay1,Az0,Az1,At0,At1]
    for (int idx = tid; idx < 24*16*3*8; idx += 256) {
        int j = idx / 384;
        int rem = idx - j*384;
        int npair = rem / 24;
        int rem2 = rem - npair*24;
        int r = rem2 >> 3;
        int t8 = rem2 & 7;
        int e4 = t8 >> 1;
        int which = t8 & 1;
        A_p[idx] = g_AT[(size_t)(j*12 + r*4 + e4)*N_ + n0 + npair*2 + which];
    }
    for (int idx = tid; idx < 128*24; idx += 256) {
        int vloc = idx / 24, j = idx - vloc*24;
        int v = v0 + vloc;
        ws[vloc*25 + j] = (v < V_) ? lw[(size_t)v*NJ_ + j] : 0.f;
    }
    if (tid < 96) trT[(tid % 3)*32 + tid/3] = trans[(n0 + tid/3)*3 + (tid % 3)];
    __syncthreads();

    // ---- packed LBS epilogue ----
    #pragma unroll
    for (int vsel = 0; vsel < 2; vsel++) {
        int vloc = col*2 + vsel;
        int v = v0 + vloc;
        #pragma unroll
        for (int np = 0; np < 4; np++) {
            u64 x2 = acc[np][vsel*3 + 0];
            u64 y2 = acc[np][vsel*3 + 1];
            u64 z2 = acc[np][vsel*3 + 2];
            u64 vr0 = *(const u64*)&trT[0*32 + nb + np*2];
            u64 vr1 = *(const u64*)&trT[1*32 + nb + np*2];
            u64 vr2 = *(const u64*)&trT[2*32 + nb + np*2];
            const float* abase = &A_p[((0*16 + ty*4 + np)*3)*8];
            #pragma unroll 4
            for (int j = 0; j < NJ_; j++) {
                u64 w2 = dup2(ws[vloc*25 + j]);
                const float* ab = abase + j*(16*3*8);
                {
                    ulonglong2 aa = *(const ulonglong2*)(ab);
                    ulonglong2 bb = *(const ulonglong2*)(ab + 4);
                    u64 t = bb.y;
                    t = fma2(aa.x, x2, t);
                    t = fma2(aa.y, y2, t);
                    t = fma2(bb.x, z2, t);
                    vr0 = fma2(w2, t, vr0);
                }
                {
                    ulonglong2 aa = *(const ulonglong2*)(ab + 8);
                    ulonglong2 bb = *(const ulonglong2*)(ab + 12);
                    u64 t = bb.y;
                    t = fma2(aa.x, x2, t);
                    t = fma2(aa.y, y2, t);
                    t = fma2(bb.x, z2, t);
                    vr1 = fma2(w2, t, vr1);
                }
                {
                    ulonglong2 aa = *(const ulonglong2*)(ab + 16);
                    ulonglong2 bb = *(const ulonglong2*)(ab + 20);
                    u64 t = bb.y;
                    t = fma2(aa.x, x2, t);
                    t = fma2(aa.y, y2, t);
                    t = fma2(bb.x, z2, t);
                    vr2 = fma2(w2, t, vr2);
                }
            }
            if (v < V_) {
                float2 p0 = unpk2(vr0), p1 = unpk2(vr1), p2 = unpk2(vr2);
                float* dst = g_verts + (size_t)v*NC_ + (n0 + nb + np*2)*3;
                *(float2*)(dst)     = make_float2(p0.x, p1.x);
                *(float2*)(dst + 2) = make_float2(p2.x, p0.y);
                *(float2*)(dst + 4) = make_float2(p1.y, p2.y);
            }
        }
    }
}

// ---------------------------------------------------------------------------
// K5 (pass2): packed keypoint GEMM [96 x 1536], split-K x24
// ---------------------------------------------------------------------------
__global__ void __launch_bounds__(256, 2)
k_pass2() {
    __shared__ float rT[16*96];
    __shared__ float vs[16*128];
    int tid = threadIdx.x;
    int tx = tid & 15, ty = tid >> 4;
    int col0 = blockIdx.x * 128;
    int sp = blockIdx.y;
    int vbeg = sp * KCH2;
    int vend = min(V_, vbeg + KCH2);

    u64 acc[6][4];
    #pragma unroll
    for (int r = 0; r < 6; r++)
        #pragma unroll
        for (int i = 0; i < 4; i++) acc[r][i] = 0ULL;

    for (int kb = vbeg; kb < vend; kb += 16) {
        int kn = min(16, vend - kb);
        __syncthreads();
        for (int idx = tid; idx < 16*96; idx += 256) {
            int kk = idx / 96, mm = idx - kk*96;
            rT[idx] = (kk < kn) ? g_RT[(size_t)(kb+kk)*96 + mm] : 0.f;
        }
        for (int idx = tid; idx < 16*128; idx += 256) {
            int kk = idx >> 7, cc = idx & 127;
            vs[idx] = (kk < kn) ? g_verts[(size_t)(kb+kk)*NC_ + col0 + cc] : 0.f;
        }
        __syncthreads();
        #pragma unroll 4
        for (int kk = 0; kk < 16; kk++) {
            u64 b2[4];
            #pragma unroll
            for (int i = 0; i < 4; i++)
                b2[i] = *(const u64*)&vs[kk*128 + 2*(tx + i*16)];
            #pragma unroll
            for (int r = 0; r < 6; r++) {
                u64 a2 = dup2(rT[kk*96 + ty*6 + r]);
                #pragma unroll
                for (int i = 0; i < 4; i++)
                    acc[r][i] = fma2(a2, b2[i], acc[r][i]);
            }
        }
    }
    float* pp = g_part + (size_t)sp * (NK_*NC_);
    #pragma unroll
    for (int r = 0; r < 6; r++) {
        int m = ty*6 + r;
        if (m < NK_) {
            #pragma unroll
            for (int i = 0; i < 4; i++) {
                float2 p = unpk2(acc[r][i]);
                *(float2*)&pp[(size_t)m*NC_ + col0 + 2*(tx + i*16)] = p;
            }
        }
    }
}

// ---------------------------------------------------------------------------
// K6: reduce split-K partials -> out[n][m][c]
// ---------------------------------------------------------------------------
__global__ void k_reduce(float* __restrict__ out) {
    int o = blockIdx.x * 256 + threadIdx.x;
    if (o >= NK_*NC_) return;
    float s = 0.f;
    #pragma unroll
    for (int sp = 0; sp < NSPLIT2; sp++) s += g_part[(size_t)sp*(NK_*NC_) + o];
    int m = o / NC_, c2 = o % NC_;
    int n = c2 / 3, c = c2 % 3;
    out[(size_t)n*(NK_*3) + m*3 + c] = s;
}

// ---------------------------------------------------------------------------
extern "C" void kernel_launch(void* const* d_in, const int* in_sizes, int n_in,
                              void* d_out, int out_size) {
    const float* pose      = (const float*)d_in[0];
    const float* betas     = (const float*)d_in[1];
    const float* trans     = (const float*)d_in[2];
    const float* vtempl    = (const float*)d_in[3];
    const float* shapedirs = (const float*)d_in[4];
    const float* Jreg      = (const float*)d_in[5];
    const float* posedirs  = (const float*)d_in[6];
    const float* lw        = (const float*)d_in[7];
    const float* body25    = (const float*)d_in[8];
    const float* face      = (const float*)d_in[9];
    const int*   parents   = (const int*)d_in[10];

    (void)in_sizes; (void)n_in; (void)out_size;

    static const int SM1 = SM1_FLOATS * sizeof(float);   // 53248 B
    cudaFuncSetAttribute(k_pass1, cudaFuncAttributeMaxDynamicSharedMemorySize, SM1);

    k_jconst<<<72 + NB_*72, 256>>>(Jreg, vtempl, shapedirs);
    k_pern<<<N_/256, 256>>>(pose, betas, vtempl, shapedirs, parents);
    k_transpose<<<(V_*96 + 255)/256, 256>>>(body25, face);
    k_pass1<<<dim3(P1_QB, N_/32), 256, SM1>>>(posedirs, shapedirs, vtempl, lw, trans);
    k_pass2<<<dim3(NC_/128, NSPLIT2), 256>>>();
    k_reduce<<<(NK_*NC_ + 255)/256, 256>>>((float*)d_out);
}

// round 10
// speedup vs baseline: 1.4984x; 1.4683x over previous
#include <cuda_runtime.h>
#include <math.h>

// Problem constants
#define N_    512
#define V_    6890
#define NJ_   24
#define NB_   10
#define KD_   218
#define Q_    (V_*3)         // 20670
#define NK_   95
#define NC_   (N_*3)         // 1536

#define P1_QB  54            // 54*384 = 20736 padded q
#define QPAD   20736
#define KPAD   224
#define NCH    14            // 224/16 k-chunks
#define NSPLIT2 24
#define KCH2    288

// ------------------------------- scratch -----------------------------------
__device__ float g_JT[NJ_*3];
__device__ float g_JS[NB_*NJ_*3];
__device__ float g_coeffT[KD_*N_];          // [k][n]
__device__ float g_AT[NJ_*12*N_];           // [j*12+e][n]
__device__ float g_B[KPAD*QPAD];            // fused B: posedirs/shapedirs/vtempl, zero padded
__device__ float g_verts[V_*NC_];           // [v][n*3+c]
__device__ float g_RT[V_*96];               // [v][m], m padded to 96
__device__ float g_part[NSPLIT2*NK_*NC_];

// ------------------------- packed f32x2 helpers -----------------------------
typedef unsigned long long u64;
__device__ __forceinline__ u64 fma2(u64 a, u64 b, u64 c) {
    u64 d; asm("fma.rn.f32x2 %0, %1, %2, %3;" : "=l"(d) : "l"(a), "l"(b), "l"(c)); return d;
}
__device__ __forceinline__ u64 dup2(float x) {
    u64 r; asm("mov.b64 %0, {%1, %1};" : "=l"(r) : "f"(x)); return r;
}
__device__ __forceinline__ float2 unpk2(u64 v) {
    float2 r; asm("mov.b64 {%0, %1}, %2;" : "=f"(r.x), "=f"(r.y) : "l"(v)); return r;
}
__device__ __forceinline__ void cp16(unsigned smem_addr, const float* g) {
    asm volatile("cp.async.ca.shared.global [%0], [%1], 16;" :: "r"(smem_addr), "l"(g));
}

// ---------------------------------------------------------------------------
// K1: joint-regressor constants
// ---------------------------------------------------------------------------
__global__ void k_jconst(const float* __restrict__ Jreg,
                         const float* __restrict__ vt,
                         const float* __restrict__ sd) {
    int o = blockIdx.x;
    int tid = threadIdx.x;
    float s = 0.f;
    if (o < 72) {
        int j = o / 3, c = o % 3;
        const float* jr = Jreg + (size_t)j * V_;
        for (int v = tid; v < V_; v += 256) s += jr[v] * vt[v*3 + c];
    } else {
        int r = o - 72;
        int b = r / 72; int r2 = r % 72;
        int j = r2 / 3, c = r2 % 3;
        const float* jr = Jreg + (size_t)j * V_;
        const float* sp = sd + (size_t)b * Q_;
        for (int v = tid; v < V_; v += 256) s += jr[v] * sp[v*3 + c];
    }
    __shared__ float red[8];
    for (int off = 16; off > 0; off >>= 1) s += __shfl_down_sync(0xffffffffu, s, off);
    if ((tid & 31) == 0) red[tid >> 5] = s;
    __syncthreads();
    if (tid == 0) {
        float t = 0.f;
        #pragma unroll
        for (int w = 0; w < 8; w++) t += red[w];
        if (o < 72) g_JT[o] = t;
        else        g_JS[o - 72] = t;
    }
}

// ---------------------------------------------------------------------------
// K2: per-n scale, coeff (transposed), FK -> A (transposed [e][n])
// ---------------------------------------------------------------------------
__global__ void k_pern(const float* __restrict__ pose,
                       const float* __restrict__ betas,
                       const float* __restrict__ vt,
                       const float* __restrict__ sd,
                       const int*   __restrict__ parents) {
    int n = blockIdx.x * blockDim.x + threadIdx.x;
    if (n >= N_) return;
    const float* be = betas + n * NB_;

    const int   iv[4]  = {2802, 6262, 2237, 6728};
    const float sg[4]  = {1.f, 1.f, -1.f, -1.f};
    float bh = 0.f;
    #pragma unroll
    for (int t = 0; t < 4; t++) {
        int q = iv[t]*3 + 1;
        float vy = vt[q];
        #pragma unroll
        for (int b = 0; b < NB_; b++) vy += be[b] * sd[(size_t)b*Q_ + q];
        bh += sg[t] * vy;
    }
    float scale = 1.66f / bh;

    const float* pn = pose + (size_t)n * NJ_ * 9;
    for (int j = 1; j < NJ_; j++) {
        #pragma unroll
        for (int e = 0; e < 9; e++) {
            float d = (e == 0 || e == 4 || e == 8) ? 1.f : 0.f;
            g_coeffT[((j-1)*9 + e)*N_ + n] = pn[j*9 + e] - d;
        }
    }
    #pragma unroll
    for (int b = 0; b < NB_; b++) g_coeffT[(207 + b)*N_ + n] = scale * be[b];
    g_coeffT[217*N_ + n] = scale;

    float Jl[NJ_][3];
    for (int j = 0; j < NJ_; j++) {
        #pragma unroll
        for (int c = 0; c < 3; c++) {
            float s = g_JT[j*3 + c];
            #pragma unroll
            for (int b = 0; b < NB_; b++) s += be[b] * g_JS[b*72 + j*3 + c];
            Jl[j][c] = scale * s;
        }
    }

    float Rg[NJ_][9], tg[NJ_][3];
    for (int i = 0; i < NJ_; i++) {
        float Ri[9];
        #pragma unroll
        for (int e = 0; e < 9; e++) Ri[e] = pn[i*9 + e];
        if (i == 0) {
            #pragma unroll
            for (int e = 0; e < 9; e++) Rg[0][e] = Ri[e];
            #pragma unroll
            for (int c = 0; c < 3; c++) tg[0][c] = Jl[0][c];
        } else {
            int p = parents[i];
            float jh[3] = {Jl[i][0]-Jl[p][0], Jl[i][1]-Jl[p][1], Jl[i][2]-Jl[p][2]};
            #pragma unroll
            for (int r = 0; r < 3; r++) {
                float p0 = Rg[p][r*3+0], p1 = Rg[p][r*3+1], p2 = Rg[p][r*3+2];
                #pragma unroll
                for (int c = 0; c < 3; c++)
                    Rg[i][r*3+c] = p0*Ri[c] + p1*Ri[3+c] + p2*Ri[6+c];
                tg[i][r] = tg[p][r] + p0*jh[0] + p1*jh[1] + p2*jh[2];
            }
        }
        #pragma unroll
        for (int r = 0; r < 3; r++) {
            g_AT[(i*12 + r*4 + 0)*N_ + n] = Rg[i][r*3+0];
            g_AT[(i*12 + r*4 + 1)*N_ + n] = Rg[i][r*3+1];
            g_AT[(i*12 + r*4 + 2)*N_ + n] = Rg[i][r*3+2];
            g_AT[(i*12 + r*4 + 3)*N_ + n] = tg[i][r] - (Rg[i][r*3+0]*Jl[i][0] +
                                                        Rg[i][r*3+1]*Jl[i][1] +
                                                        Rg[i][r*3+2]*Jl[i][2]);
        }
    }
}

// ---------------------------------------------------------------------------
// K3a: transpose keypoint regressors -> g_RT[v][96]
// ---------------------------------------------------------------------------
__global__ void k_transpose(const float* __restrict__ b25,
                            const float* __restrict__ face) {
    int idx = blockIdx.x * 256 + threadIdx.x;
    if (idx >= V_*96) return;
    int v = idx / 96, m = idx - v*96;
    float val = 0.f;
    if (m < 25)      val = b25[(size_t)m*V_ + v];
    else if (m < 95) val = face[(size_t)(m-25)*V_ + v];
    g_RT[idx] = val;
}

// ---------------------------------------------------------------------------
// K3b: build fused, zero-padded B matrix g_B[224][20736]
// ---------------------------------------------------------------------------
__global__ void k_buildB(const float* __restrict__ posedirs,
                         const float* __restrict__ shapedirs,
                         const float* __restrict__ vtempl) {
    int q = blockIdx.x * 256 + threadIdx.x;   // 0..20735 (gridDim.x = 81)
    int k = blockIdx.y;                       // 0..223
    if (q >= QPAD) return;
    float val = 0.f;
    if (q < Q_ && k < KD_) {
        if (k < 207)      val = posedirs[(size_t)k*Q_ + q];
        else if (k < 217) val = shapedirs[(size_t)(k-207)*Q_ + q];
        else              val = vtempl[q];
    }
    g_B[(size_t)k*QPAD + q] = val;
}

// ---------------------------------------------------------------------------
// K4 (pass1): f32x2 GEMM [32n x 384q, K=224] + packed LBS epilogue
// cp.async double-buffered B staging from fused g_B (no branches, no division)
// smem: cfs[224][32] (7168) + Bs[2][16][384] (12288)  = 19456 floats (77824 B)
// epilogue union in the same smem block.
// ---------------------------------------------------------------------------
#define SM1_FLOATS (KPAD*32 + 2*16*384)

__global__ void __launch_bounds__(256, 2)
k_pass1(const float* __restrict__ lw,
        const float* __restrict__ trans) {
    extern __shared__ float sm[];
    float* cfs = sm;                     // [224][32]
    float* Bs0 = sm + KPAD*32;           // [16][384]
    float* Bs1 = Bs0 + 16*384;           // [16][384]
    float* A_p = sm;                     // epi: [24][16][3][8] = 9216
    float* ws  = sm + 9216;              // epi: [128][25] = 3200
    float* trT = sm + 9216 + 3200;       // epi: [3][32]

    int tid = threadIdx.x;
    int lane = tid & 31;
    int warp = tid >> 5;
    int q0 = blockIdx.x * 384;
    int v0 = blockIdx.x * 128;
    int n0 = blockIdx.y * 32;
    int ty  = tid >> 6;                  // 0..3 (n-group of 8)
    int col = tid & 63;                  // q-group of 6
    int nb  = ty * 8;

    // ---- stage coeff (transposed), zero rows 218..223 handled by g_B pad too;
    //      g_coeffT only has KD_ rows, so pad here.
    for (int idx = tid; idx < KPAD*32; idx += 256) {
        int k = idx >> 5, nn = idx & 31;
        cfs[idx] = (k < KD_) ? g_coeffT[k*N_ + n0 + nn] : 0.f;
    }

    // staging lambda: warp w stages rows 2w, 2w+1; lane covers float4 j, j+32, j+64
    const float* gB0 = g_B + q0;
    unsigned sb0 = (unsigned)__cvta_generic_to_shared(Bs0);
    unsigned sb1 = (unsigned)__cvta_generic_to_shared(Bs1);
    #define STAGE(buf_addr, kc_) do {                                         \
        unsigned _d = (buf_addr) + (unsigned)((warp*2)*384 + lane*4)*4;       \
        const float* _s = gB0 + (size_t)((kc_) + warp*2)*QPAD + lane*4;       \
        cp16(_d,            _s);                                              \
        cp16(_d + 128*4,    _s + 128);                                        \
        cp16(_d + 256*4,    _s + 256);                                        \
        cp16(_d + 384*4,    _s + QPAD);                                       \
        cp16(_d + (384+128)*4, _s + QPAD + 128);                              \
        cp16(_d + (384+256)*4, _s + QPAD + 256);                              \
        asm volatile("cp.async.commit_group;");                               \
    } while (0)

    STAGE(sb0, 0);

    u64 acc[4][6];
    #pragma unroll
    for (int i = 0; i < 4; i++)
        #pragma unroll
        for (int j = 0; j < 6; j++) acc[i][j] = 0ULL;

    for (int c = 0; c < NCH; c++) {
        if (c + 1 < NCH) {
            STAGE((c & 1) ? sb0 : sb1, (c + 1) * 16);
            asm volatile("cp.async.wait_group 1;");
        } else {
            asm volatile("cp.async.wait_group 0;");
        }
        __syncthreads();
        const float* Bb = (c & 1) ? Bs1 : Bs0;
        const float* cb = cfs + c*16*32 + nb;
        #pragma unroll 4
        for (int kk = 0; kk < 16; kk++) {
            ulonglong2 A0 = *(const ulonglong2*)(cb + kk*32);
            ulonglong2 A1 = *(const ulonglong2*)(cb + kk*32 + 4);
            u64 a2[4] = {A0.x, A0.y, A1.x, A1.y};
            const float* br = Bb + kk*384 + col*6;
            #pragma unroll
            for (int qi = 0; qi < 6; qi++) {
                u64 b2 = dup2(br[qi]);
                #pragma unroll
                for (int np = 0; np < 4; np++)
                    acc[np][qi] = fma2(a2[np], b2, acc[np][qi]);
            }
        }
        __syncthreads();
    }

    // ---- stage epilogue data (reuses GEMM smem) ----
    // A_p layout: [j][npair(16)][r(3)][Ax0,Ax1,Ay0,Ay1,Az0,Az1,At0,At1]
    for (int idx = tid; idx < 24*16*3*8; idx += 256) {
        int j = idx / 384;
        int rem = idx - j*384;
        int npair = rem / 24;
        int rem2 = rem - npair*24;
        int r = rem2 >> 3;
        int t8 = rem2 & 7;
        int e4 = t8 >> 1;
        int which = t8 & 1;
        A_p[idx] = g_AT[(size_t)(j*12 + r*4 + e4)*N_ + n0 + npair*2 + which];
    }
    for (int idx = tid; idx < 128*24; idx += 256) {
        int vloc = idx / 24, j = idx - vloc*24;
        int v = v0 + vloc;
        ws[vloc*25 + j] = (v < V_) ? lw[(size_t)v*NJ_ + j] : 0.f;
    }
    if (tid < 96) trT[(tid % 3)*32 + tid/3] = trans[(n0 + tid/3)*3 + (tid % 3)];
    __syncthreads();

    // ---- packed LBS epilogue ----
    #pragma unroll
    for (int vsel = 0; vsel < 2; vsel++) {
        int vloc = col*2 + vsel;
        int v = v0 + vloc;
        #pragma unroll
        for (int np = 0; np < 4; np++) {
            u64 x2 = acc[np][vsel*3 + 0];
            u64 y2 = acc[np][vsel*3 + 1];
            u64 z2 = acc[np][vsel*3 + 2];
            u64 vr0 = *(const u64*)&trT[0*32 + nb + np*2];
            u64 vr1 = *(const u64*)&trT[1*32 + nb + np*2];
            u64 vr2 = *(const u64*)&trT[2*32 + nb + np*2];
            const float* abase = &A_p[((ty*4 + np)*3)*8];
            #pragma unroll 4
            for (int j = 0; j < NJ_; j++) {
                u64 w2 = dup2(ws[vloc*25 + j]);
                const float* ab = abase + j*(16*3*8);
                {
                    ulonglong2 aa = *(const ulonglong2*)(ab);
                    ulonglong2 bb = *(const ulonglong2*)(ab + 4);
                    u64 t = bb.y;
                    t = fma2(aa.x, x2, t);
                    t = fma2(aa.y, y2, t);
                    t = fma2(bb.x, z2, t);
                    vr0 = fma2(w2, t, vr0);
                }
                {
                    ulonglong2 aa = *(const ulonglong2*)(ab + 8);
                    ulonglong2 bb = *(const ulonglong2*)(ab + 12);
                    u64 t = bb.y;
                    t = fma2(aa.x, x2, t);
                    t = fma2(aa.y, y2, t);
                    t = fma2(bb.x, z2, t);
                    vr1 = fma2(w2, t, vr1);
                }
                {
                    ulonglong2 aa = *(const ulonglong2*)(ab + 16);
                    ulonglong2 bb = *(const ulonglong2*)(ab + 20);
                    u64 t = bb.y;
                    t = fma2(aa.x, x2, t);
                    t = fma2(aa.y, y2, t);
                    t = fma2(bb.x, z2, t);
                    vr2 = fma2(w2, t, vr2);
                }
            }
            if (v < V_) {
                float2 p0 = unpk2(vr0), p1 = unpk2(vr1), p2 = unpk2(vr2);
                float* dst = g_verts + (size_t)v*NC_ + (n0 + nb + np*2)*3;
                *(float2*)(dst)     = make_float2(p0.x, p1.x);
                *(float2*)(dst + 2) = make_float2(p2.x, p0.y);
                *(float2*)(dst + 4) = make_float2(p1.y, p2.y);
            }
        }
    }
    #undef STAGE
}

// ---------------------------------------------------------------------------
// K5 (pass2): packed keypoint GEMM [96 x 1536], split-K x24
// ---------------------------------------------------------------------------
__global__ void __launch_bounds__(256, 2)
k_pass2() {
    __shared__ float rT[16*96];
    __shared__ float vs[16*128];
    int tid = threadIdx.x;
    int tx = tid & 15, ty = tid >> 4;
    int col0 = blockIdx.x * 128;
    int sp = blockIdx.y;
    int vbeg = sp * KCH2;
    int vend = min(V_, vbeg + KCH2);

    u64 acc[6][4];
    #pragma unroll
    for (int r = 0; r < 6; r++)
        #pragma unroll
        for (int i = 0; i < 4; i++) acc[r][i] = 0ULL;

    for (int kb = vbeg; kb < vend; kb += 16) {
        int kn = min(16, vend - kb);
        __syncthreads();
        for (int idx = tid; idx < 16*96; idx += 256) {
            int kk = idx / 96, mm = idx - kk*96;
            rT[idx] = (kk < kn) ? g_RT[(size_t)(kb+kk)*96 + mm] : 0.f;
        }
        for (int idx = tid; idx < 16*128; idx += 256) {
            int kk = idx >> 7, cc = idx & 127;
            vs[idx] = (kk < kn) ? g_verts[(size_t)(kb+kk)*NC_ + col0 + cc] : 0.f;
        }
        __syncthreads();
        #pragma unroll 4
        for (int kk = 0; kk < 16; kk++) {
            u64 b2[4];
            #pragma unroll
            for (int i = 0; i < 4; i++)
                b2[i] = *(const u64*)&vs[kk*128 + 2*(tx + i*16)];
            #pragma unroll
            for (int r = 0; r < 6; r++) {
                u64 a2 = dup2(rT[kk*96 + ty*6 + r]);
                #pragma unroll
                for (int i = 0; i < 4; i++)
                    acc[r][i] = fma2(a2, b2[i], acc[r][i]);
            }
        }
    }
    float* pp = g_part + (size_t)sp * (NK_*NC_);
    #pragma unroll
    for (int r = 0; r < 6; r++) {
        int m = ty*6 + r;
        if (m < NK_) {
            #pragma unroll
            for (int i = 0; i < 4; i++) {
                float2 p = unpk2(acc[r][i]);
                *(float2*)&pp[(size_t)m*NC_ + col0 + 2*(tx + i*16)] = p;
            }
        }
    }
}

// ---------------------------------------------------------------------------
// K6: reduce split-K partials -> out[n][m][c]
// ---------------------------------------------------------------------------
__global__ void k_reduce(float* __restrict__ out) {
    int o = blockIdx.x * 256 + threadIdx.x;
    if (o >= NK_*NC_) return;
    float s = 0.f;
    #pragma unroll
    for (int sp = 0; sp < NSPLIT2; sp++) s += g_part[(size_t)sp*(NK_*NC_) + o];
    int m = o / NC_, c2 = o % NC_;
    int n = c2 / 3, c = c2 % 3;
    out[(size_t)n*(NK_*3) + m*3 + c] = s;
}

// ---------------------------------------------------------------------------
extern "C" void kernel_launch(void* const* d_in, const int* in_sizes, int n_in,
                              void* d_out, int out_size) {
    const float* pose      = (const float*)d_in[0];
    const float* betas     = (const float*)d_in[1];
    const float* trans     = (const float*)d_in[2];
    const float* vtempl    = (const float*)d_in[3];
    const float* shapedirs = (const float*)d_in[4];
    const float* Jreg      = (const float*)d_in[5];
    const float* posedirs  = (const float*)d_in[6];
    const float* lw        = (const float*)d_in[7];
    const float* body25    = (const float*)d_in[8];
    const float* face      = (const float*)d_in[9];
    const int*   parents   = (const int*)d_in[10];

    (void)in_sizes; (void)n_in; (void)out_size;

    static const int SM1 = SM1_FLOATS * sizeof(float);   // 77824 B
    cudaFuncSetAttribute(k_pass1, cudaFuncAttributeMaxDynamicSharedMemorySize, SM1);

    k_jconst<<<72 + NB_*72, 256>>>(Jreg, vtempl, shapedirs);
    k_pern<<<N_/256, 256>>>(pose, betas, vtempl, shapedirs, parents);
    k_transpose<<<(V_*96 + 255)/256, 256>>>(body25, face);
    k_buildB<<<dim3(QPAD/256, KPAD), 256>>>(posedirs, shapedirs, vtempl);
    k_pass1<<<dim3(P1_QB, N_/32), 256, SM1>>>(lw, trans);
    k_pass2<<<dim3(NC_/128, NSPLIT2), 256>>>();
    k_reduce<<<(NK_*NC_ + 255)/256, 256>>>((float*)d_out);
}

// round 13
// speedup vs baseline: 1.5055x; 1.0047x over previous
#include <cuda_runtime.h>
#include <math.h>

// Problem constants
#define N_    512
#define V_    6890
#define NJ_   24
#define NB_   10
#define KD_   218
#define Q_    (V_*3)         // 20670
#define NK_   95
#define NC_   (N_*3)         // 1536

#define P1_QB  54            // 54*384 = 20736 padded q
#define QPAD   20736
#define KPAD   224
#define NCH    14            // 224/16 k-chunks
#define NSPLIT2 24
#define KCH2    288

// ------------------------------- scratch -----------------------------------
__device__ float g_JT[NJ_*3];
__device__ float g_JS[NB_*NJ_*3];
__device__ float g_coeffT[KD_*N_];          // [k][n]
__device__ float g_AT[NJ_*12*N_];           // [j*12+e][n]
__device__ float g_B[KPAD*QPAD];            // fused B, tile-permuted (see k_buildB)
__device__ float g_verts[V_*NC_];           // [v][n*3+c]
__device__ float g_RT[V_*96];               // [v][m], m padded to 96
__device__ float g_part[NSPLIT2*NK_*NC_];

// ------------------------- packed f32x2 helpers -----------------------------
typedef unsigned long long u64;
__device__ __forceinline__ u64 fma2(u64 a, u64 b, u64 c) {
    u64 d; asm("fma.rn.f32x2 %0, %1, %2, %3;" : "=l"(d) : "l"(a), "l"(b), "l"(c)); return d;
}
__device__ __forceinline__ u64 dup2(float x) {
    u64 r; asm("mov.b64 %0, {%1, %1};" : "=l"(r) : "f"(x)); return r;
}
__device__ __forceinline__ float2 unpk2(u64 v) {
    float2 r; asm("mov.b64 {%0, %1}, %2;" : "=f"(r.x), "=f"(r.y) : "l"(v)); return r;
}
__device__ __forceinline__ void cp16(unsigned smem_addr, const float* g) {
    asm volatile("cp.async.ca.shared.global [%0], [%1], 16;" :: "r"(smem_addr), "l"(g));
}

// ---------------------------------------------------------------------------
// K1: joint-regressor constants
// ---------------------------------------------------------------------------
__global__ void k_jconst(const float* __restrict__ Jreg,
                         const float* __restrict__ vt,
                         const float* __restrict__ sd) {
    int o = blockIdx.x;
    int tid = threadIdx.x;
    float s = 0.f;
    if (o < 72) {
        int j = o / 3, c = o % 3;
        const float* jr = Jreg + (size_t)j * V_;
        for (int v = tid; v < V_; v += 256) s += jr[v] * vt[v*3 + c];
    } else {
        int r = o - 72;
        int b = r / 72; int r2 = r % 72;
        int j = r2 / 3, c = r2 % 3;
        const float* jr = Jreg + (size_t)j * V_;
        const float* sp = sd + (size_t)b * Q_;
        for (int v = tid; v < V_; v += 256) s += jr[v] * sp[v*3 + c];
    }
    __shared__ float red[8];
    for (int off = 16; off > 0; off >>= 1) s += __shfl_down_sync(0xffffffffu, s, off);
    if ((tid & 31) == 0) red[tid >> 5] = s;
    __syncthreads();
    if (tid == 0) {
        float t = 0.f;
        #pragma unroll
        for (int w = 0; w < 8; w++) t += red[w];
        if (o < 72) g_JT[o] = t;
        else        g_JS[o - 72] = t;
    }
}

// ---------------------------------------------------------------------------
// K2: per-n scale, coeff (transposed), FK -> A (transposed [e][n])
// ---------------------------------------------------------------------------
__global__ void k_pern(const float* __restrict__ pose,
                       const float* __restrict__ betas,
                       const float* __restrict__ vt,
                       const float* __restrict__ sd,
                       const int*   __restrict__ parents) {
    int n = blockIdx.x * blockDim.x + threadIdx.x;
    if (n >= N_) return;
    const float* be = betas + n * NB_;

    const int   iv[4]  = {2802, 6262, 2237, 6728};
    const float sg[4]  = {1.f, 1.f, -1.f, -1.f};
    float bh = 0.f;
    #pragma unroll
    for (int t = 0; t < 4; t++) {
        int q = iv[t]*3 + 1;
        float vy = vt[q];
        #pragma unroll
        for (int b = 0; b < NB_; b++) vy += be[b] * sd[(size_t)b*Q_ + q];
        bh += sg[t] * vy;
    }
    float scale = 1.66f / bh;

    const float* pn = pose + (size_t)n * NJ_ * 9;
    for (int j = 1; j < NJ_; j++) {
        #pragma unroll
        for (int e = 0; e < 9; e++) {
            float d = (e == 0 || e == 4 || e == 8) ? 1.f : 0.f;
            g_coeffT[((j-1)*9 + e)*N_ + n] = pn[j*9 + e] - d;
        }
    }
    #pragma unroll
    for (int b = 0; b < NB_; b++) g_coeffT[(207 + b)*N_ + n] = scale * be[b];
    g_coeffT[217*N_ + n] = scale;

    float Jl[NJ_][3];
    for (int j = 0; j < NJ_; j++) {
        #pragma unroll
        for (int c = 0; c < 3; c++) {
            float s = g_JT[j*3 + c];
            #pragma unroll
            for (int b = 0; b < NB_; b++) s += be[b] * g_JS[b*72 + j*3 + c];
            Jl[j][c] = scale * s;
        }
    }

    float Rg[NJ_][9], tg[NJ_][3];
    for (int i = 0; i < NJ_; i++) {
        float Ri[9];
        #pragma unroll
        for (int e = 0; e < 9; e++) Ri[e] = pn[i*9 + e];
        if (i == 0) {
            #pragma unroll
            for (int e = 0; e < 9; e++) Rg[0][e] = Ri[e];
            #pragma unroll
            for (int c = 0; c < 3; c++) tg[0][c] = Jl[0][c];
        } else {
            int p = parents[i];
            float jh[3] = {Jl[i][0]-Jl[p][0], Jl[i][1]-Jl[p][1], Jl[i][2]-Jl[p][2]};
            #pragma unroll
            for (int r = 0; r < 3; r++) {
                float p0 = Rg[p][r*3+0], p1 = Rg[p][r*3+1], p2 = Rg[p][r*3+2];
                #pragma unroll
                for (int c = 0; c < 3; c++)
                    Rg[i][r*3+c] = p0*Ri[c] + p1*Ri[3+c] + p2*Ri[6+c];
                tg[i][r] = tg[p][r] + p0*jh[0] + p1*jh[1] + p2*jh[2];
            }
        }
        #pragma unroll
        for (int r = 0; r < 3; r++) {
            g_AT[(i*12 + r*4 + 0)*N_ + n] = Rg[i][r*3+0];
            g_AT[(i*12 + r*4 + 1)*N_ + n] = Rg[i][r*3+1];
            g_AT[(i*12 + r*4 + 2)*N_ + n] = Rg[i][r*3+2];
            g_AT[(i*12 + r*4 + 3)*N_ + n] = tg[i][r] - (Rg[i][r*3+0]*Jl[i][0] +
                                                        Rg[i][r*3+1]*Jl[i][1] +
                                                        Rg[i][r*3+2]*Jl[i][2]);
        }
    }
}

// ---------------------------------------------------------------------------
// K3a: transpose keypoint regressors -> g_RT[v][96]
// ---------------------------------------------------------------------------
__global__ void k_transpose(const float* __restrict__ b25,
                            const float* __restrict__ face) {
    int idx = blockIdx.x * 256 + threadIdx.x;
    if (idx >= V_*96) return;
    int v = idx / 96, m = idx - v*96;
    float val = 0.f;
    if (m < 25)      val = b25[(size_t)m*V_ + v];
    else if (m < 95) val = face[(size_t)(m-25)*V_ + v];
    g_RT[idx] = val;
}

// ---------------------------------------------------------------------------
// K3b: build fused B, TILE-PERMUTED for conflict-free LDS:
// within each 384-q tile t, position s holds original q = t*384 + (s&63)*6 + (s>>6)
// so consumer thread `col` reads Bs[qi*64 + col] -> lane-consecutive words.
// ---------------------------------------------------------------------------
__global__ void k_buildB(const float* __restrict__ posedirs,
                         const float* __restrict__ shapedirs,
                         const float* __restrict__ vtempl) {
    int p = blockIdx.x * 256 + threadIdx.x;   // 0..20735
    int k = blockIdx.y;                       // 0..223
    if (p >= QPAD) return;
    int t = p / 384;
    int s = p - t*384;
    int q = t*384 + (s & 63)*6 + (s >> 6);    // original q this slot holds
    float val = 0.f;
    if (q < Q_ && k < KD_) {
        if (k < 207)      val = posedirs[(size_t)k*Q_ + q];
        else if (k < 217) val = shapedirs[(size_t)(k-207)*Q_ + q];
        else              val = vtempl[q];
    }
    g_B[(size_t)k*QPAD + p] = val;
}

// ---------------------------------------------------------------------------
// K4 (pass1): f32x2 GEMM [32n x 384q, K=224] + packed LBS epilogue
// 3-stage cp.async ring (one __syncthreads per chunk), conflict-free B loads.
// smem: cfs[224][32] (7168) + Bs[3][16][384] (18432) = 25600 floats (102400 B)
// ---------------------------------------------------------------------------
#define SM1_FLOATS (KPAD*32 + 3*16*384)

__global__ void __launch_bounds__(256, 2)
k_pass1(const float* __restrict__ lw,
        const float* __restrict__ trans) {
    extern __shared__ float sm[];
    float* cfs = sm;                     // [224][32]
    float* Bs  = sm + KPAD*32;           // [3][16][384]
    float* A_p = sm;                     // epi: [24][16][3][8] = 9216
    float* ws  = sm + 9216;              // epi: [128][25] = 3200
    float* trT = sm + 9216 + 3200;       // epi: [3][32]

    int tid = threadIdx.x;
    int lane = tid & 31;
    int warp = tid >> 5;
    int q0 = blockIdx.x * 384;
    int v0 = blockIdx.x * 128;
    int n0 = blockIdx.y * 32;
    int ty  = tid >> 6;                  // 0..3 (n-group of 8)
    int col = tid & 63;                  // q-group of 6 (owns q = q0+col*6+qi)
    int nb  = ty * 8;

    // ---- stage coeff (transposed), pad rows 218..223 with zeros ----
    for (int idx = tid; idx < KPAD*32; idx += 256) {
        int k = idx >> 5, nn = idx & 31;
        cfs[idx] = (k < KD_) ? g_coeffT[k*N_ + n0 + nn] : 0.f;
    }

    const float* gB0 = g_B + q0;
    unsigned sbase = (unsigned)__cvta_generic_to_shared(Bs);
    // warp stages rows 2w,2w+1 of the 16-row chunk; lane covers 3 float4 per row
    #define STAGE(bufi, kc_) do {                                             \
        unsigned _d = sbase + (unsigned)((bufi)*6144 + (warp*2)*384 + lane*4)*4; \
        const float* _s = gB0 + (size_t)((kc_) + warp*2)*QPAD + lane*4;       \
        cp16(_d,               _s);                                           \
        cp16(_d + 128*4,       _s + 128);                                     \
        cp16(_d + 256*4,       _s + 256);                                     \
        cp16(_d + 384*4,       _s + QPAD);                                    \
        cp16(_d + (384+128)*4, _s + QPAD + 128);                              \
        cp16(_d + (384+256)*4, _s + QPAD + 256);                              \
        asm volatile("cp.async.commit_group;");                               \
    } while (0)

    STAGE(0, 0);
    STAGE(1, 16);

    u64 acc[4][6];
    #pragma unroll
    for (int i = 0; i < 4; i++)
        #pragma unroll
        for (int j = 0; j < 6; j++) acc[i][j] = 0ULL;

    int bufc = 0;
    for (int c = 0; c < NCH; c++) {
        if (c + 2 < NCH) {
            int bn = bufc + 2; if (bn >= 3) bn -= 3;
            STAGE(bn, (c + 2) * 16);
            asm volatile("cp.async.wait_group 2;");
        } else if (c + 2 == NCH) {
            asm volatile("cp.async.wait_group 1;");
        } else {
            asm volatile("cp.async.wait_group 0;");
        }
        __syncthreads();
        const float* Bb = Bs + bufc*6144;
        const float* cb = cfs + c*16*32 + nb;
        #pragma unroll 4
        for (int kk = 0; kk < 16; kk++) {
            ulonglong2 A0 = *(const ulonglong2*)(cb + kk*32);
            ulonglong2 A1 = *(const ulonglong2*)(cb + kk*32 + 4);
            u64 a2[4] = {A0.x, A0.y, A1.x, A1.y};
            const float* br = Bb + kk*384 + col;      // +qi*64: conflict-free
            #pragma unroll
            for (int qi = 0; qi < 6; qi++) {
                u64 b2 = dup2(br[qi*64]);
                #pragma unroll
                for (int np = 0; np < 4; np++)
                    acc[np][qi] = fma2(a2[np], b2, acc[np][qi]);
            }
        }
        if (++bufc == 3) bufc = 0;
    }
    __syncthreads();   // protect smem reuse (cfs/Bs -> A_p/ws/trT)

    // ---- stage epilogue data ----
    // A_p layout: [j][npair(16)][r(3)][Ax0,Ax1,Ay0,Ay1,Az0,Az1,At0,At1]
    for (int idx = tid; idx < 24*16*3*8; idx += 256) {
        int j = idx / 384;
        int rem = idx - j*384;
        int npair = rem / 24;
        int rem2 = rem - npair*24;
        int r = rem2 >> 3;
        int t8 = rem2 & 7;
        int e4 = t8 >> 1;
        int which = t8 & 1;
        A_p[idx] = g_AT[(size_t)(j*12 + r*4 + e4)*N_ + n0 + npair*2 + which];
    }
    for (int idx = tid; idx < 128*24; idx += 256) {
        int vloc = idx / 24, j = idx - vloc*24;
        int v = v0 + vloc;
        ws[vloc*25 + j] = (v < V_) ? lw[(size_t)v*NJ_ + j] : 0.f;
    }
    if (tid < 96) trT[(tid % 3)*32 + tid/3] = trans[(n0 + tid/3)*3 + (tid % 3)];
    __syncthreads();

    // ---- packed LBS epilogue: np outer, A loaded once, both verts inner ----
    #pragma unroll
    for (int np = 0; np < 4; np++) {
        u64 vr[2][3];
        #pragma unroll
        for (int r = 0; r < 3; r++) {
            u64 t0 = *(const u64*)&trT[r*32 + nb + np*2];
            vr[0][r] = t0;
            vr[1][r] = t0;
        }
        const float* abase = &A_p[((ty*4 + np)*3)*8];
        #pragma unroll 4
        for (int j = 0; j < NJ_; j++) {
            const float* ab = abase + j*(16*3*8);
            ulonglong2 r0a = *(const ulonglong2*)(ab);
            ulonglong2 r0b = *(const ulonglong2*)(ab + 4);
            ulonglong2 r1a = *(const ulonglong2*)(ab + 8);
            ulonglong2 r1b = *(const ulonglong2*)(ab + 12);
            ulonglong2 r2a = *(const ulonglong2*)(ab + 16);
            ulonglong2 r2b = *(const ulonglong2*)(ab + 20);
            #pragma unroll
            for (int vsel = 0; vsel < 2; vsel++) {
                u64 w2 = dup2(ws[(col*2 + vsel)*25 + j]);
                u64 x2 = acc[np][vsel*3 + 0];
                u64 y2 = acc[np][vsel*3 + 1];
                u64 z2 = acc[np][vsel*3 + 2];
                u64 t;
                t = r0b.y;
                t = fma2(r0a.x, x2, t);
                t = fma2(r0a.y, y2, t);
                t = fma2(r0b.x, z2, t);
                vr[vsel][0] = fma2(w2, t, vr[vsel][0]);
                t = r1b.y;
                t = fma2(r1a.x, x2, t);
                t = fma2(r1a.y, y2, t);
                t = fma2(r1b.x, z2, t);
                vr[vsel][1] = fma2(w2, t, vr[vsel][1]);
                t = r2b.y;
                t = fma2(r2a.x, x2, t);
                t = fma2(r2a.y, y2, t);
                t = fma2(r2b.x, z2, t);
                vr[vsel][2] = fma2(w2, t, vr[vsel][2]);
            }
        }
        #pragma unroll
        for (int vsel = 0; vsel < 2; vsel++) {
            int v = v0 + col*2 + vsel;
            if (v < V_) {
                float2 p0 = unpk2(vr[vsel][0]), p1 = unpk2(vr[vsel][1]), p2 = unpk2(vr[vsel][2]);
                float* dst = g_verts + (size_t)v*NC_ + (n0 + nb + np*2)*3;
                *(float2*)(dst)     = make_float2(p0.x, p1.x);
                *(float2*)(dst + 2) = make_float2(p2.x, p0.y);
                *(float2*)(dst + 4) = make_float2(p1.y, p2.y);
            }
        }
    }
    #undef STAGE
}

// ---------------------------------------------------------------------------
// K5 (pass2): packed keypoint GEMM [96 x 1536], split-K x24
// ---------------------------------------------------------------------------
__global__ void __launch_bounds__(256, 2)
k_pass2() {
    __shared__ float rT[16*96];
    __shared__ float vs[16*128];
    int tid = threadIdx.x;
    int tx = tid & 15, ty = tid >> 4;
    int col0 = blockIdx.x * 128;
    int sp = blockIdx.y;
    int vbeg = sp * KCH2;
    int vend = min(V_, vbeg + KCH2);

    u64 acc[6][4];
    #pragma unroll
    for (int r = 0; r < 6; r++)
        #pragma unroll
        for (int i = 0; i < 4; i++) acc[r][i] = 0ULL;

    for (int kb = vbeg; kb < vend; kb += 16) {
        int kn = min(16, vend - kb);
        __syncthreads();
        for (int idx = tid; idx < 16*96; idx += 256) {
            int kk = idx / 96, mm = idx - kk*96;
            rT[idx] = (kk < kn) ? g_RT[(size_t)(kb+kk)*96 + mm] : 0.f;
        }
        for (int idx = tid; idx < 16*128; idx += 256) {
            int kk = idx >> 7, cc = idx & 127;
            vs[idx] = (kk < kn) ? g_verts[(size_t)(kb+kk)*NC_ + col0 + cc] : 0.f;
        }
        __syncthreads();
        #pragma unroll 4
        for (int kk = 0; kk < 16; kk++) {
            u64 b2[4];
            #pragma unroll
            for (int i = 0; i < 4; i++)
                b2[i] = *(const u64*)&vs[kk*128 + 2*(tx + i*16)];
            #pragma unroll
            for (int r = 0; r < 6; r++) {
                u64 a2 = dup2(rT[kk*96 + ty*6 + r]);
                #pragma unroll
                for (int i = 0; i < 4; i++)
                    acc[r][i] = fma2(a2, b2[i], acc[r][i]);
            }
        }
    }
    float* pp = g_part + (size_t)sp * (NK_*NC_);
    #pragma unroll
    for (int r = 0; r < 6; r++) {
        int m = ty*6 + r;
        if (m < NK_) {
            #pragma unroll
            for (int i = 0; i < 4; i++) {
                float2 p = unpk2(acc[r][i]);
                *(float2*)&pp[(size_t)m*NC_ + col0 + 2*(tx + i*16)] = p;
            }
        }
    }
}

// ---------------------------------------------------------------------------
// K6: reduce split-K partials -> out[n][m][c]
// ---------------------------------------------------------------------------
__global__ void k_reduce(float* __restrict__ out) {
    int o = blockIdx.x * 256 + threadIdx.x;
    if (o >= NK_*NC_) return;
    float s = 0.f;
    #pragma unroll
    for (int sp = 0; sp < NSPLIT2; sp++) s += g_part[(size_t)sp*(NK_*NC_) + o];
    int m = o / NC_, c2 = o % NC_;
    int n = c2 / 3, c = c2 % 3;
    out[(size_t)n*(NK_*3) + m*3 + c] = s;
}

// ---------------------------------------------------------------------------
extern "C" void kernel_launch(void* const* d_in, const int* in_sizes, int n_in,
                              void* d_out, int out_size) {
    const float* pose      = (const float*)d_in[0];
    const float* betas     = (const float*)d_in[1];
    const float* trans     = (const float*)d_in[2];
    const float* vtempl    = (const float*)d_in[3];
    const float* shapedirs = (const float*)d_in[4];
    const float* Jreg      = (const float*)d_in[5];
    const float* posedirs  = (const float*)d_in[6];
    const float* lw        = (const float*)d_in[7];
    const float* body25    = (const float*)d_in[8];
    const float* face      = (const float*)d_in[9];
    const int*   parents   = (const int*)d_in[10];

    (void)in_sizes; (void)n_in; (void)out_size;

    static const int SM1 = SM1_FLOATS * sizeof(float);   // 102400 B
    cudaFuncSetAttribute(k_pass1, cudaFuncAttributeMaxDynamicSharedMemorySize, SM1);

    k_jconst<<<72 + NB_*72, 256>>>(Jreg, vtempl, shapedirs);
    k_pern<<<N_/256, 256>>>(pose, betas, vtempl, shapedirs, parents);
    k_transpose<<<(V_*96 + 255)/256, 256>>>(body25, face);
    k_buildB<<<dim3(QPAD/256, KPAD), 256>>>(posedirs, shapedirs, vtempl);
    k_pass1<<<dim3(P1_QB, N_/32), 256, SM1>>>(lw, trans);
    k_pass2<<<dim3(NC_/128, NSPLIT2), 256>>>();
    k_reduce<<<(NK_*NC_ + 255)/256, 256>>>((float*)d_out);
}